// round 15
// baseline (speedup 1.0000x reference)
#include <cuda_runtime.h>
#include <cuda_fp16.h>
#include <cstdint>

#define BB 32
#define CC 256
#define HW 32
#define EE 8
#define KTOT 2304                 // 9 taps * 256 ic
#define KELEM (CC*CC*9)           // per-expert weight elements
#define BN_EPS 1e-5f

// ---------------- scratch (device globals, no allocations) ----------------
__device__ float  g_r[BB*EE];
__device__ __half g_kw [(size_t)BB*CC*KTOT];     // fp16 weights bank1 [b][oc][tap][ic]
__device__ __half g_kw2[(size_t)BB*CC*KTOT];     // fp16 weights bank2
__device__ __half g_xh[(size_t)BB*HW*HW*CC];     // fp16 NHWC input  [b][pos][ic]
__device__ __half g_o1[(size_t)BB*HW*HW*CC];     // fp16 NHWC intermediate

// ---------------- helpers ----------------
__device__ __forceinline__ uint32_t smem_u32(const void* p) {
    uint32_t a;
    asm("{ .reg .u64 t; cvta.to.shared.u64 t, %1; cvt.u32.u64 %0, t; }" : "=r"(a) : "l"(p));
    return a;
}
__device__ __forceinline__ uint32_t pack2h(__half a, __half b) {
    return (uint32_t)__half_as_ushort(a) | ((uint32_t)__half_as_ushort(b) << 16);
}

#define CP_ASYNC16(dst, src) \
    asm volatile("cp.async.cg.shared.global [%0], [%1], 16;" :: "r"(dst), "l"(src))
#define CP_ASYNC16Z(dst, src, sz) \
    asm volatile("cp.async.cg.shared.global [%0], [%1], 16, %2;" :: "r"(dst), "l"(src), "r"(sz))
#define CP_COMMIT()  asm volatile("cp.async.commit_group;")
#define CP_WAIT_1()  asm volatile("cp.async.wait_group 1;")

#define BAR_PAIR(id) asm volatile("bar.sync %0, 64;" :: "r"(id) : "memory")

#define LDSM_X4(r0,r1,r2,r3,addr) \
    asm volatile("ldmatrix.sync.aligned.m8n8.x4.shared.b16 {%0,%1,%2,%3}, [%4];" \
        : "=r"(r0),"=r"(r1),"=r"(r2),"=r"(r3) : "r"(addr))
#define MMA16816(d,a0,a1,a2,a3,b0,b1) \
    asm volatile("mma.sync.aligned.m16n8k16.row.col.f32.f16.f16.f32 " \
        "{%0,%1,%2,%3},{%4,%5,%6,%7},{%8,%9},{%0,%1,%2,%3};" \
        : "+f"((d)[0]),"+f"((d)[1]),"+f"((d)[2]),"+f"((d)[3]) \
        : "r"(a0),"r"(a1),"r"(a2),"r"(a3),"r"(b0),"r"(b1))

// ============================================================================
// Router: GAP -> Linear(C,E) -> sigmoid   (grid=B, block=256)
// ============================================================================
__global__ void router_kernel(const float* __restrict__ x,
                              const float* __restrict__ rw,
                              const float* __restrict__ rb) {
    __shared__ float means[CC];
    int b = blockIdx.x;
    int wid = threadIdx.x >> 5, lane = threadIdx.x & 31;
    const float4* xb = (const float4*)(x + (size_t)b*CC*(HW*HW));
    #pragma unroll 4
    for (int i = 0; i < 32; i++) {
        int c = wid*32 + i;
        const float4* p = xb + (size_t)c*(HW*HW/4);
        float s = 0.f;
        #pragma unroll
        for (int j = 0; j < 8; j++) {
            float4 v = p[j*32 + lane];
            s += v.x + v.y + v.z + v.w;
        }
        #pragma unroll
        for (int o = 16; o; o >>= 1) s += __shfl_xor_sync(0xFFFFFFFFu, s, o);
        if (lane == 0) means[c] = s * (1.0f/(HW*HW));
    }
    __syncthreads();
    if (threadIdx.x < EE) {
        int c = threadIdx.x;
        float d = rb[c];
        #pragma unroll 8
        for (int k = 0; k < CC; k++) d = fmaf(means[k], rw[c*CC + k], d);
        g_r[b*EE + c] = 1.0f / (1.0f + expf(-d));
    }
}

// ============================================================================
// NCHW fp32 -> NHWC fp16: coalesced loads -> smem transpose -> packed stores.
// grid = (32 b * 32 h), block 256.
// ============================================================================
__global__ void x2h_kernel(const float* __restrict__ x) {
    __shared__ float xs[CC*32];                    // 32KB: [ic][w]
    int blk = blockIdx.x;
    int b = blk >> 5, h = blk & 31;
    int tid = threadIdx.x;

    const float* src = x + ((size_t)b*CC*HW + h)*HW;
    #pragma unroll
    for (int ico = 0; ico < 8; ico++) {
        int ic = ico*32 + (tid >> 3);
        float4 v = *(const float4*)(src + (size_t)ic*(HW*HW) + (tid & 7)*4);
        *(float4*)&xs[ic*32 + (tid & 7)*4] = v;
    }
    __syncthreads();

    int w = tid & 31;
    int ic0 = (tid >> 5) * 32;
    __half vals[32];
    #pragma unroll
    for (int j = 0; j < 32; j++)
        vals[j] = __float2half_rn(xs[(ic0 + j)*32 + w]);

    __half* dst = g_xh + (((size_t)b*HW*HW) + h*HW + w)*CC + ic0;
    #pragma unroll
    for (int q = 0; q < 4; q++) {
        uint4 u;
        u.x = pack2h(vals[q*8+0], vals[q*8+1]);
        u.y = pack2h(vals[q*8+2], vals[q*8+3]);
        u.z = pack2h(vals[q*8+4], vals[q*8+5]);
        u.w = pack2h(vals[q*8+6], vals[q*8+7]);
        *(uint4*)(dst + q*8) = u;
    }
}

// ============================================================================
// Combine v2 (4 oc / block, uint2 stores):
//   g_kw*[b][oc][tap][ic] = sum_e r[b,e]*w[e][oc][ic][tap]
// grid = (512 = 64 ocg x 8 icb, 2 bank), block = 288.
// ============================================================================
__global__ void combine_kernel(const float* __restrict__ w1,
                               const float* __restrict__ w2) {
    __shared__ float sw[4][EE][288];
    __shared__ float rs[BB*EE];
    int t = threadIdx.x;
    if (t < BB*EE) rs[t] = g_r[t];

    int oc0 = (blockIdx.x >> 3) * 4;
    int icb = blockIdx.x & 7;
    const float* wb = blockIdx.y ? w2 : w1;
    __half* dst = blockIdx.y ? g_kw2 : g_kw;

    const float* srcb = wb + (size_t)oc0*KTOT + icb*288;
    #pragma unroll
    for (int j = 0; j < 32; j++) {
        int l = j*288 + t;
        int oc = l / 2304;
        int rem = l - oc*2304;
        int e = rem / 288;
        int pos = rem - e*288;
        sw[oc][e][pos] = srcb[(size_t)e*KELEM + (size_t)oc*KTOT + pos];
    }
    __syncthreads();

    int ocl = t / 72;
    int rem = t - ocl*72;
    int tap = rem >> 3;        // 0..8
    int icq = rem & 7;
    int icl = icq * 4;

    float v[EE][4];
    #pragma unroll
    for (int e = 0; e < EE; e++)
        #pragma unroll
        for (int i = 0; i < 4; i++)
            v[e][i] = sw[ocl][e][(icl + i)*9 + tap];

    size_t dbase = ((size_t)(oc0 + ocl)*9 + tap)*256 + icb*32 + icl;
    #pragma unroll
    for (int b = 0; b < BB; b++) {
        float a0=0.f, a1=0.f, a2=0.f, a3=0.f;
        #pragma unroll
        for (int e = 0; e < EE; e++) {
            float r = rs[b*EE + e];
            a0 = fmaf(r, v[e][0], a0); a1 = fmaf(r, v[e][1], a1);
            a2 = fmaf(r, v[e][2], a2); a3 = fmaf(r, v[e][3], a3);
        }
        uint2 u;
        u.x = pack2h(__float2half_rn(a0), __float2half_rn(a1));
        u.y = pack2h(__float2half_rn(a2), __float2half_rn(a3));
        *(uint2*)(dst + (size_t)b*(CC*KTOT) + dbase) = u;
    }
}

// ============================================================================
// NHWC implicit-GEMM conv3x3 + BN + [residual] + ReLU
// grid = (8 ptile, 32 b, 2 nblk), block = 256 (8 warps: 2M x 4N), 2 CTA/SM.
// DESYNC: per-CTA tap-order rotation (tap = (si + shift) % 9) so co-resident
// CTAs' LDSM phases overlap each other's MMA phases (break barrier convoy).
// ============================================================================
#define RP 144                                    // row pitch bytes
#define SLAB_BYTES (204*RP)                       // 29376
#define WT_BYTES   (128*RP)                       // 18432
#define SMEM_BYTES (2*SLAB_BYTES + 3*WT_BYTES)    // 114048

template<bool RESID, int KWSEL>
__global__ void __launch_bounds__(256, 2)
conv_mma_kernel(const float* __restrict__ x_orig,
                const float* __restrict__ gg, const float* __restrict__ gb,
                const float* __restrict__ gm, const float* __restrict__ gv,
                float* __restrict__ out_param) {
    extern __shared__ __align__(1024) char dsm[];

    const int ptile = blockIdx.x;          // 0..7  -> 128 positions (4 h rows)
    const int b     = blockIdx.y;
    const int nblk  = blockIdx.z;          // 0..1  -> oc halves
    const int tid   = threadIdx.x;
    const int lid   = tid & 31;
    const int wid   = tid >> 5;
    const int wm    = wid & 1;             // M warp (64 pos)
    const int wn    = wid >> 1;            // N warp (32 oc)
    const int h0    = ptile * 4;
    const int barid = 1 + wn;              // pair barrier id
    const int tshift = (blockIdx.x & 3) * 2;   // per-CTA tap rotation

    const uint32_t sbase = smem_u32(dsm);
    const uint32_t SLABA[2] = { sbase, sbase + SLAB_BYTES };
    const uint32_t WTA[3]   = { sbase + 2*SLAB_BYTES,
                                sbase + 2*SLAB_BYTES + WT_BYTES,
                                sbase + 2*SLAB_BYTES + 2*WT_BYTES };

    const __half* xin = (RESID ? g_o1 : g_xh) + (size_t)b*(HW*HW*CC);   // NHWC
    const __half* kwb = (KWSEL ? g_kw2 : g_kw)
                      + (size_t)b*(CC*KTOT) + (size_t)(nblk*128)*KTOT;

    // ---- zero the w = -1 / w = 32 pad rows in both slabs (once) ----
    for (int i = tid; i < 864; i += 256) {
        int buf = i / 432, rem = i % 432;
        int r = rem / 36, word = rem % 36;
        int srow = (r >> 1)*34 + (r & 1)*33;
        *(uint32_t*)(dsm + buf*SLAB_BYTES + srow*RP + word*4) = 0u;
    }

    // ---- per-warp weight fill: warp fills its pair's 16 oc rows ----
    const int wrow0 = wn*32 + wm*16 + (lid >> 3);
    const __half* wsrc0 = kwb + (size_t)wrow0*KTOT + (lid & 7)*8;
    const uint32_t woff0 = wrow0*RP + (lid & 7)*16;
    auto fillW = [&](int off, uint32_t buf) {     // off in elements into [tap][ic]
        #pragma unroll
        for (int it = 0; it < 4; it++)
            CP_ASYNC16(buf + woff0 + it*4*RP, wsrc0 + (size_t)it*4*KTOT + off);
    };
    // ---- slab fill: 192 data rows x 64 ic, CTA-wide striped ----
    auto fillSlab = [&](int icc, uint32_t buf) {
        const int ic0 = icc * 64;
        #pragma unroll
        for (int it = 0; it < 6; it++) {
            int idx = it*256 + tid;
            int row = idx >> 3, ck = idx & 7;
            int hp = row >> 5, w = row & 31;
            int hh = h0 - 1 + hp;
            uint32_t ok = ((unsigned)hh < HW) ? 16u : 0u;
            int hcl = hh < 0 ? 0 : (hh > 31 ? 31 : hh);
            const __half* src = xin + ((size_t)(hcl*HW + w)*CC + ic0 + ck*8);
            int srow = hp*34 + w + 1;
            CP_ASYNC16Z(buf + srow*RP + ck*16, src, ok);
        }
    };

    // ---- per-thread fragment base offsets ----
    const int lrow = lid & 15;
    const int hi16 = lid >> 4;
    uint32_t aOff[4];
    #pragma unroll
    for (int mt = 0; mt < 4; mt++) {
        int p = wm*64 + mt*16 + lrow;
        aOff[mt] = (uint32_t)(((p >> 5)*34 + (p & 31))*RP + hi16*16);
    }
    uint32_t bOff[2];
    #pragma unroll
    for (int nt = 0; nt < 2; nt++) {
        int oc = wn*32 + nt*16 + lrow;
        bOff[nt] = (uint32_t)(oc*RP + hi16*16);
    }

    float acc[4][4][4];
    #pragma unroll
    for (int mt = 0; mt < 4; mt++)
        #pragma unroll
        for (int nb = 0; nb < 4; nb++)
            #pragma unroll
            for (int k = 0; k < 4; k++) acc[mt][nb][k] = 0.f;

    // prologue: G0 = slab0 + W(stage0) ; G1 = W(stage1)
    {
        int t0 = tshift;                    // tap of stage 0
        int t1 = tshift + 1; if (t1 >= 9) t1 -= 9;
        fillSlab(0, SLABA[0]); fillW(t0*256, WTA[0]); CP_COMMIT();
        fillW(t1*256, WTA[1]); CP_COMMIT();
    }

    #pragma unroll 1
    for (int icc = 0; icc < 4; icc++) {
        const uint32_t slab = SLABA[icc & 1];
        #pragma unroll
        for (int si = 0; si < 9; si++) {
            int tap = si + tshift; if (tap >= 9) tap -= 9;
            int dy = tap / 3;
            int drow = (dy*34 + (tap - dy*3)) * RP;
            const uint32_t wbuf = WTA[si % 3];         // stage-indexed ring

            // address math BEFORE the wait/barrier (no smem access)
            uint32_t aAddr[4];
            #pragma unroll
            for (int mt = 0; mt < 4; mt++) aAddr[mt] = slab + aOff[mt] + drow;
            uint32_t bAddr0 = wbuf + bOff[0];
            uint32_t bAddr1 = wbuf + bOff[1];

            CP_WAIT_1();
            if (si == 0) __syncthreads();              // slab visibility (CTA-wide)
            else         BAR_PAIR(barid);              // weight pair sync only

            #pragma unroll
            for (int k = 0; k < 4; k++) {
                uint32_t a[4][4], bm[2][4];
                #pragma unroll
                for (int mt = 0; mt < 4; mt++)
                    LDSM_X4(a[mt][0], a[mt][1], a[mt][2], a[mt][3],
                            aAddr[mt] + k*32);
                LDSM_X4(bm[0][0], bm[0][1], bm[0][2], bm[0][3], bAddr0 + k*32);
                LDSM_X4(bm[1][0], bm[1][1], bm[1][2], bm[1][3], bAddr1 + k*32);
                #pragma unroll
                for (int mt = 0; mt < 4; mt++) {
                    #pragma unroll
                    for (int nt = 0; nt < 2; nt++) {
                        MMA16816(acc[mt][nt*2+0], a[mt][0],a[mt][1],a[mt][2],a[mt][3],
                                 bm[nt][0], bm[nt][2]);
                        MMA16816(acc[mt][nt*2+1], a[mt][0],a[mt][1],a[mt][2],a[mt][3],
                                 bm[nt][1], bm[nt][3]);
                    }
                }
            }

            // prefetch weights for stage si+2 (possibly next icc, same perm)
            {
                int si2 = si + 2, icc2 = icc;
                if (si2 >= 9) { si2 -= 9; icc2++; }
                if (icc2 < 4) {
                    int tap2 = si2 + tshift; if (tap2 >= 9) tap2 -= 9;
                    fillW(tap2*256 + icc2*64, WTA[(si + 2) % 3]);
                }
            }
            if (si == 2 && icc < 3) fillSlab(icc + 1, SLABA[(icc + 1) & 1]);
            CP_COMMIT();
        }
    }

    __syncthreads();   // smem reuse barrier

    // ======================= epilogue (smem-staged) =======================
    if (RESID) {
        // stage raw acc as [oc][pos] fp32, pitch 132
        float* ep = (float*)dsm;
        #pragma unroll
        for (int nb = 0; nb < 4; nb++) {
            int ocl = wn*32 + nb*8 + (lid & 3)*2;
            #pragma unroll
            for (int mt = 0; mt < 4; mt++) {
                #pragma unroll
                for (int rh = 0; rh < 2; rh++) {
                    int ptl = wm*64 + mt*16 + (lid >> 2) + rh*8;
                    ep[ocl*132 + ptl]       = acc[mt][nb][rh*2+0];
                    ep[(ocl+1)*132 + ptl]   = acc[mt][nb][rh*2+1];
                }
            }
        }
        __syncthreads();
        // stream out: warp iterates 16 oc rows, lanes cover 128 pos (512B)
        #pragma unroll 4
        for (int r = 0; r < 16; r++) {
            int ocl = wid*16 + r;
            int ocg = nblk*128 + ocl;
            float sgl = gg[ocg] * rsqrtf(gv[ocg] + BN_EPS);
            float sft = gb[ocg] - gm[ocg] * sgl;
            size_t gbase = ((size_t)b*CC + ocg)*(HW*HW) + ptile*128 + lid*4;
            float4 a = *(float4*)(ep + ocl*132 + lid*4);
            float4 rv = *(const float4*)(x_orig + gbase);
            float4 o;
            o.x = fmaxf(fmaf(a.x, sgl, sft) + rv.x, 0.f);
            o.y = fmaxf(fmaf(a.y, sgl, sft) + rv.y, 0.f);
            o.z = fmaxf(fmaf(a.z, sgl, sft) + rv.z, 0.f);
            o.w = fmaxf(fmaf(a.w, sgl, sft) + rv.w, 0.f);
            *(float4*)(out_param + gbase) = o;
        }
    } else {
        // BN+ReLU here, stage as [pos][oc] fp16, pitch 136
        __half* ep = (__half*)dsm;
        #pragma unroll
        for (int nb = 0; nb < 4; nb++) {
            int ocl = wn*32 + nb*8 + (lid & 3)*2;
            int ocg = nblk*128 + ocl;
            float s0 = gg[ocg]   * rsqrtf(gv[ocg]   + BN_EPS);
            float t0 = gb[ocg]   - gm[ocg]   * s0;
            float s1 = gg[ocg+1] * rsqrtf(gv[ocg+1] + BN_EPS);
            float t1 = gb[ocg+1] - gm[ocg+1] * s1;
            #pragma unroll
            for (int mt = 0; mt < 4; mt++) {
                #pragma unroll
                for (int rh = 0; rh < 2; rh++) {
                    int ptl = wm*64 + mt*16 + (lid >> 2) + rh*8;
                    float v0 = fmaxf(fmaf(acc[mt][nb][rh*2+0], s0, t0), 0.f);
                    float v1 = fmaxf(fmaf(acc[mt][nb][rh*2+1], s1, t1), 0.f);
                    *(uint32_t*)&ep[ptl*136 + ocl] =
                        pack2h(__float2half_rn(v0), __float2half_rn(v1));
                }
            }
        }
        __syncthreads();
        // stream out: 2 pos rows per warp-iteration; 16 lanes x 16B = 128 ch/row
        #pragma unroll 4
        for (int rr = 0; rr < 8; rr++) {
            int posr = wid*16 + rr*2 + hi16;            // 0..127
            int cl   = (lid & 15) * 8;                  // 0..120
            const __half* src = ep + posr*136 + cl;
            __half* dstp = g_o1 + ((size_t)b*(HW*HW) + ptile*128 + posr)*CC
                         + nblk*128 + cl;
            *(uint4*)dstp = *(const uint4*)src;
        }
    }
}

// ============================================================================
extern "C" void kernel_launch(void* const* d_in, const int* in_sizes, int n_in,
                              void* d_out, int out_size) {
    const float* x  = (const float*)d_in[0];
    const float* rw = (const float*)d_in[1];
    const float* rb = (const float*)d_in[2];
    const float* w1 = (const float*)d_in[3];
    const float* w2 = (const float*)d_in[4];
    const float* g1 = (const float*)d_in[5];
    const float* b1 = (const float*)d_in[6];
    const float* m1 = (const float*)d_in[7];
    const float* v1 = (const float*)d_in[8];
    const float* g2 = (const float*)d_in[9];
    const float* b2 = (const float*)d_in[10];
    const float* m2 = (const float*)d_in[11];
    const float* v2 = (const float*)d_in[12];
    float* out = (float*)d_out;

    cudaFuncSetAttribute((const void*)conv_mma_kernel<false,0>,
                         cudaFuncAttributeMaxDynamicSharedMemorySize, SMEM_BYTES);
    cudaFuncSetAttribute((const void*)conv_mma_kernel<true,1>,
                         cudaFuncAttributeMaxDynamicSharedMemorySize, SMEM_BYTES);

    dim3 cgrid(8, BB, 2);
    dim3 cbgrid(512, 2);

    router_kernel<<<BB, 256>>>(x, rw, rb);
    x2h_kernel<<<BB*HW, 256>>>(x);
    combine_kernel<<<cbgrid, 288>>>(w1, w2);
    conv_mma_kernel<false,0><<<cgrid, 256, SMEM_BYTES>>>(x, g1, b1, m1, v1, nullptr);
    conv_mma_kernel<true,1><<<cgrid, 256, SMEM_BYTES>>>(x, g2, b2, m2, v2, out);
}

// round 16
// speedup vs baseline: 1.1326x; 1.1326x over previous
#include <cuda_runtime.h>
#include <cuda_fp16.h>
#include <cstdint>

#define BB 32
#define CC 256
#define HW 32
#define EE 8
#define KTOT 2304                 // 9 taps * 256 ic
#define KELEM (CC*CC*9)           // per-expert weight elements
#define BN_EPS 1e-5f

// ---------------- scratch (device globals, no allocations) ----------------
__device__ float  g_r[BB*EE];
__device__ float  g_ps[BB*HW*CC];                // per-(b,h) channel partial sums
__device__ __half g_kw [(size_t)BB*CC*KTOT];     // fp16 weights bank1 [b][oc][tap][ic]
__device__ __half g_kw2[(size_t)BB*CC*KTOT];     // fp16 weights bank2
__device__ __half g_xh[(size_t)BB*HW*HW*CC];     // fp16 NHWC input  [b][pos][ic]
__device__ __half g_o1[(size_t)BB*HW*HW*CC];     // fp16 NHWC intermediate

// ---------------- helpers ----------------
__device__ __forceinline__ uint32_t smem_u32(const void* p) {
    uint32_t a;
    asm("{ .reg .u64 t; cvta.to.shared.u64 t, %1; cvt.u32.u64 %0, t; }" : "=r"(a) : "l"(p));
    return a;
}
__device__ __forceinline__ uint32_t pack2h(__half a, __half b) {
    return (uint32_t)__half_as_ushort(a) | ((uint32_t)__half_as_ushort(b) << 16);
}

#define CP_ASYNC16(dst, src) \
    asm volatile("cp.async.cg.shared.global [%0], [%1], 16;" :: "r"(dst), "l"(src))
#define CP_ASYNC16Z(dst, src, sz) \
    asm volatile("cp.async.cg.shared.global [%0], [%1], 16, %2;" :: "r"(dst), "l"(src), "r"(sz))
#define CP_COMMIT()  asm volatile("cp.async.commit_group;")
#define CP_WAIT_1()  asm volatile("cp.async.wait_group 1;")

#define BAR_PAIR(id) asm volatile("bar.sync %0, 64;" :: "r"(id) : "memory")

#define LDSM_X4(r0,r1,r2,r3,addr) \
    asm volatile("ldmatrix.sync.aligned.m8n8.x4.shared.b16 {%0,%1,%2,%3}, [%4];" \
        : "=r"(r0),"=r"(r1),"=r"(r2),"=r"(r3) : "r"(addr))
#define MMA16816(d,a0,a1,a2,a3,b0,b1) \
    asm volatile("mma.sync.aligned.m16n8k16.row.col.f32.f16.f16.f32 " \
        "{%0,%1,%2,%3},{%4,%5,%6,%7},{%8,%9},{%0,%1,%2,%3};" \
        : "+f"((d)[0]),"+f"((d)[1]),"+f"((d)[2]),"+f"((d)[3]) \
        : "r"(a0),"r"(a1),"r"(a2),"r"(a3),"r"(b0),"r"(b1))

// ============================================================================
// NCHW fp32 -> NHWC fp16 + per-(b,h) channel partial sums into g_ps.
// grid = (32 b * 32 h), block 256.
// ============================================================================
__global__ void x2h_kernel(const float* __restrict__ x) {
    __shared__ float xs[CC*32];                    // 32KB: [ic][w]
    int blk = blockIdx.x;
    int b = blk >> 5, h = blk & 31;
    int tid = threadIdx.x;

    const float* src = x + ((size_t)b*CC*HW + h)*HW;
    #pragma unroll
    for (int ico = 0; ico < 8; ico++) {
        int ic = ico*32 + (tid >> 3);
        float4 v = *(const float4*)(src + (size_t)ic*(HW*HW) + (tid & 7)*4);
        *(float4*)&xs[ic*32 + (tid & 7)*4] = v;
    }
    __syncthreads();

    // per-channel partial sum over w (rotated index -> conflict-free)
    {
        float s = 0.f;
        #pragma unroll 8
        for (int j = 0; j < 32; j++)
            s += xs[tid*32 + ((tid + j) & 31)];
        g_ps[((size_t)b*HW + h)*CC + tid] = s;
    }

    int w = tid & 31;
    int ic0 = (tid >> 5) * 32;
    __half vals[32];
    #pragma unroll
    for (int j = 0; j < 32; j++)
        vals[j] = __float2half_rn(xs[(ic0 + j)*32 + w]);

    __half* dst = g_xh + (((size_t)b*HW*HW) + h*HW + w)*CC + ic0;
    #pragma unroll
    for (int q = 0; q < 4; q++) {
        uint4 u;
        u.x = pack2h(vals[q*8+0], vals[q*8+1]);
        u.y = pack2h(vals[q*8+2], vals[q*8+3]);
        u.z = pack2h(vals[q*8+4], vals[q*8+5]);
        u.w = pack2h(vals[q*8+6], vals[q*8+7]);
        *(uint4*)(dst + q*8) = u;
    }
}

// ============================================================================
// Router tail: reduce g_ps over h -> means -> Linear(C,E) -> sigmoid.
// grid = 32 (b), block = 256.
// ============================================================================
__global__ void router2_kernel(const float* __restrict__ rw,
                               const float* __restrict__ rb) {
    __shared__ float means[CC];
    int b = blockIdx.x, c = threadIdx.x;
    float s = 0.f;
    #pragma unroll 8
    for (int h = 0; h < HW; h++)
        s += g_ps[((size_t)b*HW + h)*CC + c];
    means[c] = s * (1.0f/(HW*HW));
    __syncthreads();
    if (c < EE) {
        float d = rb[c];
        #pragma unroll 8
        for (int k = 0; k < CC; k++) d = fmaf(means[k], rw[c*CC + k], d);
        g_r[b*EE + c] = 1.0f / (1.0f + expf(-d));
    }
}

// ============================================================================
// Combine v2 (4 oc / block, uint2 stores):
//   g_kw*[b][oc][tap][ic] = sum_e r[b,e]*w[e][oc][ic][tap]
// grid = (512 = 64 ocg x 8 icb, 2 bank), block = 288.
// ============================================================================
__global__ void combine_kernel(const float* __restrict__ w1,
                               const float* __restrict__ w2) {
    __shared__ float sw[4][EE][288];
    __shared__ float rs[BB*EE];
    int t = threadIdx.x;
    if (t < BB*EE) rs[t] = g_r[t];

    int oc0 = (blockIdx.x >> 3) * 4;
    int icb = blockIdx.x & 7;
    const float* wb = blockIdx.y ? w2 : w1;
    __half* dst = blockIdx.y ? g_kw2 : g_kw;

    const float* srcb = wb + (size_t)oc0*KTOT + icb*288;
    #pragma unroll
    for (int j = 0; j < 32; j++) {
        int l = j*288 + t;
        int oc = l / 2304;
        int rem = l - oc*2304;
        int e = rem / 288;
        int pos = rem - e*288;
        sw[oc][e][pos] = srcb[(size_t)e*KELEM + (size_t)oc*KTOT + pos];
    }
    __syncthreads();

    int ocl = t / 72;
    int rem = t - ocl*72;
    int tap = rem >> 3;        // 0..8
    int icq = rem & 7;
    int icl = icq * 4;

    float v[EE][4];
    #pragma unroll
    for (int e = 0; e < EE; e++)
        #pragma unroll
        for (int i = 0; i < 4; i++)
            v[e][i] = sw[ocl][e][(icl + i)*9 + tap];

    size_t dbase = ((size_t)(oc0 + ocl)*9 + tap)*256 + icb*32 + icl;
    #pragma unroll
    for (int b = 0; b < BB; b++) {
        float a0=0.f, a1=0.f, a2=0.f, a3=0.f;
        #pragma unroll
        for (int e = 0; e < EE; e++) {
            float r = rs[b*EE + e];
            a0 = fmaf(r, v[e][0], a0); a1 = fmaf(r, v[e][1], a1);
            a2 = fmaf(r, v[e][2], a2); a3 = fmaf(r, v[e][3], a3);
        }
        uint2 u;
        u.x = pack2h(__float2half_rn(a0), __float2half_rn(a1));
        u.y = pack2h(__float2half_rn(a2), __float2half_rn(a3));
        *(uint2*)(dst + (size_t)b*(CC*KTOT) + dbase) = u;
    }
}

// ============================================================================
// NHWC implicit-GEMM conv3x3 + BN + [residual] + ReLU  (R14 mainloop, proven)
// grid = (8 ptile, 32 b, 2 nblk), block = 256 (8 warps: 2M x 4N), 2 CTA/SM.
// ============================================================================
#define RP 144                                    // row pitch bytes
#define SLAB_BYTES (204*RP)                       // 29376
#define WT_BYTES   (128*RP)                       // 18432
#define SMEM_BYTES (2*SLAB_BYTES + 3*WT_BYTES)    // 114048

template<bool RESID, int KWSEL>
__global__ void __launch_bounds__(256, 2)
conv_mma_kernel(const float* __restrict__ x_orig,
                const float* __restrict__ gg, const float* __restrict__ gb,
                const float* __restrict__ gm, const float* __restrict__ gv,
                float* __restrict__ out_param) {
    extern __shared__ __align__(1024) char dsm[];

    const int ptile = blockIdx.x;          // 0..7  -> 128 positions (4 h rows)
    const int b     = blockIdx.y;
    const int nblk  = blockIdx.z;          // 0..1  -> oc halves
    const int tid   = threadIdx.x;
    const int lid   = tid & 31;
    const int wid   = tid >> 5;
    const int wm    = wid & 1;             // M warp (64 pos)
    const int wn    = wid >> 1;            // N warp (32 oc)
    const int h0    = ptile * 4;
    const int barid = 1 + wn;              // pair barrier id

    const uint32_t sbase = smem_u32(dsm);
    const uint32_t SLABA[2] = { sbase, sbase + SLAB_BYTES };
    const uint32_t WTA[3]   = { sbase + 2*SLAB_BYTES,
                                sbase + 2*SLAB_BYTES + WT_BYTES,
                                sbase + 2*SLAB_BYTES + 2*WT_BYTES };

    const __half* xin = (RESID ? g_o1 : g_xh) + (size_t)b*(HW*HW*CC);   // NHWC
    const __half* kwb = (KWSEL ? g_kw2 : g_kw)
                      + (size_t)b*(CC*KTOT) + (size_t)(nblk*128)*KTOT;

    // ---- zero the w = -1 / w = 32 pad rows in both slabs (once) ----
    for (int i = tid; i < 864; i += 256) {
        int buf = i / 432, rem = i % 432;
        int r = rem / 36, word = rem % 36;
        int srow = (r >> 1)*34 + (r & 1)*33;
        *(uint32_t*)(dsm + buf*SLAB_BYTES + srow*RP + word*4) = 0u;
    }

    // ---- per-warp weight fill: warp fills its pair's 16 oc rows ----
    const int wrow0 = wn*32 + wm*16 + (lid >> 3);
    const __half* wsrc0 = kwb + (size_t)wrow0*KTOT + (lid & 7)*8;
    const uint32_t woff0 = wrow0*RP + (lid & 7)*16;
    auto fillW = [&](int off, uint32_t buf) {     // off in elements into [tap][ic]
        #pragma unroll
        for (int it = 0; it < 4; it++)
            CP_ASYNC16(buf + woff0 + it*4*RP, wsrc0 + (size_t)it*4*KTOT + off);
    };
    // ---- slab fill: 192 data rows x 64 ic, CTA-wide striped ----
    auto fillSlab = [&](int icc, uint32_t buf) {
        const int ic0 = icc * 64;
        #pragma unroll
        for (int it = 0; it < 6; it++) {
            int idx = it*256 + tid;
            int row = idx >> 3, ck = idx & 7;
            int hp = row >> 5, w = row & 31;
            int hh = h0 - 1 + hp;
            uint32_t ok = ((unsigned)hh < HW) ? 16u : 0u;
            int hcl = hh < 0 ? 0 : (hh > 31 ? 31 : hh);
            const __half* src = xin + ((size_t)(hcl*HW + w)*CC + ic0 + ck*8);
            int srow = hp*34 + w + 1;
            CP_ASYNC16Z(buf + srow*RP + ck*16, src, ok);
        }
    };

    // ---- per-thread fragment base offsets ----
    const int lrow = lid & 15;
    const int hi16 = lid >> 4;
    uint32_t aOff[4];
    #pragma unroll
    for (int mt = 0; mt < 4; mt++) {
        int p = wm*64 + mt*16 + lrow;
        aOff[mt] = (uint32_t)(((p >> 5)*34 + (p & 31))*RP + hi16*16);
    }
    uint32_t bOff[2];
    #pragma unroll
    for (int nt = 0; nt < 2; nt++) {
        int oc = wn*32 + nt*16 + lrow;
        bOff[nt] = (uint32_t)(oc*RP + hi16*16);
    }

    float acc[4][4][4];
    #pragma unroll
    for (int mt = 0; mt < 4; mt++)
        #pragma unroll
        for (int nb = 0; nb < 4; nb++)
            #pragma unroll
            for (int k = 0; k < 4; k++) acc[mt][nb][k] = 0.f;

    // prologue: G0 = slab0 + W0 ; G1 = W1
    fillSlab(0, SLABA[0]); fillW(0, WTA[0]); CP_COMMIT();
    fillW(256, WTA[1]); CP_COMMIT();

    #pragma unroll 1
    for (int icc = 0; icc < 4; icc++) {
        const uint32_t slab = SLABA[icc & 1];
        #pragma unroll
        for (int tap = 0; tap < 9; tap++) {
            const int dy = tap / 3, dx = tap - dy*3;
            const int drow = (dy*34 + dx)*RP;          // compile-time per tap
            const uint32_t wbuf = WTA[tap % 3];

            // address math BEFORE the wait/barrier (no smem access)
            uint32_t aAddr[4];
            #pragma unroll
            for (int mt = 0; mt < 4; mt++) aAddr[mt] = slab + aOff[mt] + drow;
            uint32_t bAddr0 = wbuf + bOff[0];
            uint32_t bAddr1 = wbuf + bOff[1];

            CP_WAIT_1();
            if (tap == 0) __syncthreads();             // slab visibility (CTA-wide)
            else          BAR_PAIR(barid);             // weight pair sync only

            #pragma unroll
            for (int k = 0; k < 4; k++) {
                uint32_t a[4][4], bm[2][4];
                #pragma unroll
                for (int mt = 0; mt < 4; mt++)
                    LDSM_X4(a[mt][0], a[mt][1], a[mt][2], a[mt][3],
                            aAddr[mt] + k*32);
                LDSM_X4(bm[0][0], bm[0][1], bm[0][2], bm[0][3], bAddr0 + k*32);
                LDSM_X4(bm[1][0], bm[1][1], bm[1][2], bm[1][3], bAddr1 + k*32);
                #pragma unroll
                for (int mt = 0; mt < 4; mt++) {
                    #pragma unroll
                    for (int nt = 0; nt < 2; nt++) {
                        MMA16816(acc[mt][nt*2+0], a[mt][0],a[mt][1],a[mt][2],a[mt][3],
                                 bm[nt][0], bm[nt][2]);
                        MMA16816(acc[mt][nt*2+1], a[mt][0],a[mt][1],a[mt][2],a[mt][3],
                                 bm[nt][1], bm[nt][3]);
                    }
                }
            }

            // prefetch stage s+2 weights; slab for next icc at tap==2
            if (tap < 7)       fillW((tap+2)*256 + icc*64,     WTA[(tap+2) % 3]);
            else if (icc < 3)  fillW((tap-7)*256 + (icc+1)*64, WTA[(tap+2) % 3]);
            if (tap == 2 && icc < 3) fillSlab(icc + 1, SLABA[(icc + 1) & 1]);
            CP_COMMIT();
        }
    }

    __syncthreads();   // smem reuse barrier

    // ======================= epilogue (smem-staged) =======================
    if (RESID) {
        // stage raw acc as [oc][pos] fp32, pitch 132
        float* ep = (float*)dsm;
        #pragma unroll
        for (int nb = 0; nb < 4; nb++) {
            int ocl = wn*32 + nb*8 + (lid & 3)*2;
            #pragma unroll
            for (int mt = 0; mt < 4; mt++) {
                #pragma unroll
                for (int rh = 0; rh < 2; rh++) {
                    int ptl = wm*64 + mt*16 + (lid >> 2) + rh*8;
                    ep[ocl*132 + ptl]       = acc[mt][nb][rh*2+0];
                    ep[(ocl+1)*132 + ptl]   = acc[mt][nb][rh*2+1];
                }
            }
        }
        __syncthreads();
        // stream out: warp iterates 16 oc rows, lanes cover 128 pos (512B)
        #pragma unroll 4
        for (int r = 0; r < 16; r++) {
            int ocl = wid*16 + r;
            int ocg = nblk*128 + ocl;
            float sgl = gg[ocg] * rsqrtf(gv[ocg] + BN_EPS);
            float sft = gb[ocg] - gm[ocg] * sgl;
            size_t gbase = ((size_t)b*CC + ocg)*(HW*HW) + ptile*128 + lid*4;
            float4 a = *(float4*)(ep + ocl*132 + lid*4);
            float4 rv = *(const float4*)(x_orig + gbase);
            float4 o;
            o.x = fmaxf(fmaf(a.x, sgl, sft) + rv.x, 0.f);
            o.y = fmaxf(fmaf(a.y, sgl, sft) + rv.y, 0.f);
            o.z = fmaxf(fmaf(a.z, sgl, sft) + rv.z, 0.f);
            o.w = fmaxf(fmaf(a.w, sgl, sft) + rv.w, 0.f);
            *(float4*)(out_param + gbase) = o;
        }
    } else {
        // BN+ReLU here, stage as [pos][oc] fp16, pitch 136
        __half* ep = (__half*)dsm;
        #pragma unroll
        for (int nb = 0; nb < 4; nb++) {
            int ocl = wn*32 + nb*8 + (lid & 3)*2;
            int ocg = nblk*128 + ocl;
            float s0 = gg[ocg]   * rsqrtf(gv[ocg]   + BN_EPS);
            float t0 = gb[ocg]   - gm[ocg]   * s0;
            float s1 = gg[ocg+1] * rsqrtf(gv[ocg+1] + BN_EPS);
            float t1 = gb[ocg+1] - gm[ocg+1] * s1;
            #pragma unroll
            for (int mt = 0; mt < 4; mt++) {
                #pragma unroll
                for (int rh = 0; rh < 2; rh++) {
                    int ptl = wm*64 + mt*16 + (lid >> 2) + rh*8;
                    float v0 = fmaxf(fmaf(acc[mt][nb][rh*2+0], s0, t0), 0.f);
                    float v1 = fmaxf(fmaf(acc[mt][nb][rh*2+1], s1, t1), 0.f);
                    *(uint32_t*)&ep[ptl*136 + ocl] =
                        pack2h(__float2half_rn(v0), __float2half_rn(v1));
                }
            }
        }
        __syncthreads();
        // stream out: 2 pos rows per warp-iteration; 16 lanes x 16B = 128 ch/row
        #pragma unroll 4
        for (int rr = 0; rr < 8; rr++) {
            int posr = wid*16 + rr*2 + hi16;            // 0..127
            int cl   = (lid & 15) * 8;                  // 0..120
            const __half* src = ep + posr*136 + cl;
            __half* dstp = g_o1 + ((size_t)b*(HW*HW) + ptile*128 + posr)*CC
                         + nblk*128 + cl;
            *(uint4*)dstp = *(const uint4*)src;
        }
    }
}

// ============================================================================
extern "C" void kernel_launch(void* const* d_in, const int* in_sizes, int n_in,
                              void* d_out, int out_size) {
    const float* x  = (const float*)d_in[0];
    const float* rw = (const float*)d_in[1];
    const float* rb = (const float*)d_in[2];
    const float* w1 = (const float*)d_in[3];
    const float* w2 = (const float*)d_in[4];
    const float* g1 = (const float*)d_in[5];
    const float* b1 = (const float*)d_in[6];
    const float* m1 = (const float*)d_in[7];
    const float* v1 = (const float*)d_in[8];
    const float* g2 = (const float*)d_in[9];
    const float* b2 = (const float*)d_in[10];
    const float* m2 = (const float*)d_in[11];
    const float* v2 = (const float*)d_in[12];
    float* out = (float*)d_out;

    cudaFuncSetAttribute((const void*)conv_mma_kernel<false,0>,
                         cudaFuncAttributeMaxDynamicSharedMemorySize, SMEM_BYTES);
    cudaFuncSetAttribute((const void*)conv_mma_kernel<true,1>,
                         cudaFuncAttributeMaxDynamicSharedMemorySize, SMEM_BYTES);

    dim3 cgrid(8, BB, 2);
    dim3 cbgrid(512, 2);

    x2h_kernel<<<BB*HW, 256>>>(x);
    router2_kernel<<<BB, 256>>>(rw, rb);
    combine_kernel<<<cbgrid, 288>>>(w1, w2);
    conv_mma_kernel<false,0><<<cgrid, 256, SMEM_BYTES>>>(x, g1, b1, m1, v1, nullptr);
    conv_mma_kernel<true,1><<<cgrid, 256, SMEM_BYTES>>>(x, g2, b2, m2, v2, out);
}